// round 12
// baseline (speedup 1.0000x reference)
#include <cuda_runtime.h>
#include <cuda_bf16.h>
#include <cstdint>

#define GEMM_GRID 148
#define BSZ       128
#define DEL       196608          // 3*256*256
#define KC        32              // K elements per chunk (fp8: 32B smem rows)
#define NCHUNK    (DEL / KC)      // 6144
#define REGP      0.01f
#define NUM_ITER  100
#define SW        12              // smem row stride in uint32 words (8 data + 4 pad)

// -------- deterministic global scratch (no allocations allowed) --------
__device__ float g_P [GEMM_GRID][BSZ * BSZ]; // split-K partial dot products
__device__ float g_xp[GEMM_GRID][BSZ];       // partial ||delta||^2
__device__ float g_yp[GEMM_GRID][BSZ];       // partial ||target||^2
__device__ float g_x2[BSZ];
__device__ float g_y2[BSZ];
__device__ float g_C [BSZ * BSZ];            // cost matrix

// pack 4 fp32 -> 4 e4m3 bytes (byte0 = a .. byte3 = d)
__device__ __forceinline__ uint32_t pack_e4m3x4(float a, float b, float c, float d) {
    uint16_t lo, hi;
    asm("cvt.rn.satfinite.e4m3x2.f32 %0, %1, %2;" : "=h"(lo) : "f"(b), "f"(a));
    asm("cvt.rn.satfinite.e4m3x2.f32 %0, %1, %2;" : "=h"(hi) : "f"(d), "f"(c));
    return (uint32_t)lo | ((uint32_t)hi << 16);
}

// ============================================================
// Kernel 1: split-K GEMM (fp8 e4m3 m16n8k32) + fp32 row norms.
//   512 threads / 16 warps. 2-deep register prefetch + double-buffered
//   smem, 1 BAR/chunk:
//     iter i: LDG(i+2) ; MMA(buf=chunk i) ; STS(i+1 -> buf^1) ; BAR
//   LDG->STS distance = one full chunk cycle (> loaded DRAM latency).
// ============================================================
__global__ void __launch_bounds__(512, 1)
gemm_kernel(const float* __restrict__ imgs,
            const float* __restrict__ imgsw,
            const float* __restrict__ tgt)
{
    __shared__ uint32_t sA[2][BSZ * SW];
    __shared__ uint32_t sB[2][BSZ * SW];

    const int tid  = threadIdx.x;
    const int lane = tid & 31;
    const int warp = tid >> 5;           // 0..15

    // loader mapping: 8 lanes cover one row's 128B (fp32); warp covers 8 rows
    const int g8 = lane >> 3;            // 0..3
    const int f  = lane & 7;             // float4 index in row chunk

    // mma mapping: 4x4 warp grid of 32x32 tiles
    const int m0 = (warp & 3) * 32;
    const int n0 = (warp >> 2) * 32;
    const int g  = lane >> 2;
    const int tg = lane & 3;

    float acc[2][4][4];
    #pragma unroll
    for (int a = 0; a < 2; a++)
        #pragma unroll
        for (int b = 0; b < 4; b++)
            #pragma unroll
            for (int cc = 0; cc < 4; cc++) acc[a][b][cc] = 0.f;

    float sx[2] = {0.f, 0.f};
    float sy[2] = {0.f, 0.f};

    float4 rA0[2], rW0[2], rT0[2];       // prefetch set 0 (24 floats)
    float4 rA1[2], rW1[2], rT1[2];       // prefetch set 1

    auto ldg_chunk = [&](int c, float4* a, float4* w, float4* t) {
        #pragma unroll
        for (int k = 0; k < 2; k++) {
            const int row = warp * 8 + g8 + 4 * k;        // 0..127
            const size_t fidx = (size_t)row * (DEL / 4) + (size_t)c * 8 + f;
            a[k] = reinterpret_cast<const float4*>(imgs )[fidx];
            w[k] = reinterpret_cast<const float4*>(imgsw)[fidx];
            t[k] = reinterpret_cast<const float4*>(tgt  )[fidx];
        }
    };

    auto sts_chunk = [&](const float4* a, const float4* w, const float4* t, int st) {
        #pragma unroll
        for (int k = 0; k < 2; k++) {
            const int row = warp * 8 + g8 + 4 * k;
            float4 d4 = make_float4(w[k].x - a[k].x, w[k].y - a[k].y,
                                    w[k].z - a[k].z, w[k].w - a[k].w);
            sx[k] += d4.x * d4.x + d4.y * d4.y + d4.z * d4.z + d4.w * d4.w;
            sy[k] += t[k].x * t[k].x + t[k].y * t[k].y
                   + t[k].z * t[k].z + t[k].w * t[k].w;
            sA[st][row * SW + f] = pack_e4m3x4(d4.x, d4.y, d4.z, d4.w);
            sB[st][row * SW + f] = pack_e4m3x4(t[k].x, t[k].y, t[k].z, t[k].w);
        }
    };

    auto mma_buf = [&](int st) {
        uint32_t A0[2], A1[2], A2[2], A3[2];
        #pragma unroll
        for (int mt = 0; mt < 2; mt++) {
            const int row = m0 + mt * 16 + g;
            A0[mt] = sA[st][ row      * SW + tg    ];
            A1[mt] = sA[st][(row + 8) * SW + tg    ];
            A2[mt] = sA[st][ row      * SW + tg + 4];
            A3[mt] = sA[st][(row + 8) * SW + tg + 4];
        }
        #pragma unroll
        for (int nt = 0; nt < 4; nt++) {
            const int nrow = n0 + nt * 8 + g;
            uint32_t b0 = sB[st][nrow * SW + tg    ];
            uint32_t b1 = sB[st][nrow * SW + tg + 4];
            #pragma unroll
            for (int mt = 0; mt < 2; mt++) {
                asm volatile(
                    "mma.sync.aligned.m16n8k32.row.col.f32.e4m3.e4m3.f32 "
                    "{%0,%1,%2,%3}, {%4,%5,%6,%7}, {%8,%9}, {%0,%1,%2,%3};"
                    : "+f"(acc[mt][nt][0]), "+f"(acc[mt][nt][1]),
                      "+f"(acc[mt][nt][2]), "+f"(acc[mt][nt][3])
                    : "r"(A0[mt]), "r"(A1[mt]), "r"(A2[mt]), "r"(A3[mt]),
                      "r"(b0), "r"(b1));
            }
        }
    };

    const int c0 = blockIdx.x;
    const int G  = GEMM_GRID;

    // prologue: chunk c0 -> set0 -> buf0 ; chunk c0+G -> set1 (held)
    ldg_chunk(c0, rA0, rW0, rT0);
    if (c0 + G < NCHUNK) ldg_chunk(c0 + G, rA1, rW1, rT1);
    sts_chunk(rA0, rW0, rT0, 0);
    __syncthreads();

    int st = 0;
    for (int c = c0; c < NCHUNK; c += 2 * G) {
        // sub-iter A: chunk c in buf st; set0 free
        if (c + 2 * G < NCHUNK) ldg_chunk(c + 2 * G, rA0, rW0, rT0);
        mma_buf(st);
        if (c + G < NCHUNK) sts_chunk(rA1, rW1, rT1, st ^ 1);
        __syncthreads();
        st ^= 1;
        if (c + G >= NCHUNK) break;

        // sub-iter B: chunk c+G in buf st; set1 free
        if (c + 3 * G < NCHUNK) ldg_chunk(c + 3 * G, rA1, rW1, rT1);
        mma_buf(st);
        if (c + 2 * G < NCHUNK) sts_chunk(rA0, rW0, rT0, st ^ 1);
        __syncthreads();
        st ^= 1;
    }

    // write split-K partials (each warp its 32x32 tile)
    float* P = g_P[blockIdx.x];
    #pragma unroll
    for (int mt = 0; mt < 2; mt++) {
        #pragma unroll
        for (int nt = 0; nt < 4; nt++) {
            const int row = m0 + mt * 16 + g;
            const int col = n0 + nt * 8 + tg * 2;
            float2* p0 = reinterpret_cast<float2*>(&P[ row      * BSZ + col]);
            float2* p1 = reinterpret_cast<float2*>(&P[(row + 8) * BSZ + col]);
            *p0 = make_float2(acc[mt][nt][0], acc[mt][nt][1]);
            *p1 = make_float2(acc[mt][nt][2], acc[mt][nt][3]);
        }
    }

    // norm partials: 8 lanes (f=0..7) share a row
    #pragma unroll
    for (int k = 0; k < 2; k++) {
        float x = sx[k], y = sy[k];
        x += __shfl_xor_sync(0xFFFFFFFFu, x, 1);
        x += __shfl_xor_sync(0xFFFFFFFFu, x, 2);
        x += __shfl_xor_sync(0xFFFFFFFFu, x, 4);
        y += __shfl_xor_sync(0xFFFFFFFFu, y, 1);
        y += __shfl_xor_sync(0xFFFFFFFFu, y, 2);
        y += __shfl_xor_sync(0xFFFFFFFFu, y, 4);
        if (f == 0) {
            const int row = warp * 8 + g8 + 4 * k;
            g_xp[blockIdx.x][row] = x;
            g_yp[blockIdx.x][row] = y;
        }
    }
}

// ============================================================
// Kernel 2: reduce norm partials
// ============================================================
__global__ void norm_reduce_kernel()
{
    const int t = threadIdx.x;
    float sxv = 0.f, syv = 0.f;
    #pragma unroll 4
    for (int c = 0; c < GEMM_GRID; c++) {
        sxv += g_xp[c][t];
        syv += g_yp[c][t];
    }
    g_x2[t] = sxv;
    g_y2[t] = syv;
}

// ============================================================
// Kernel 3: reduce split-K partials, build C.
// ============================================================
__global__ void __launch_bounds__(512, 1)
cost_kernel()
{
    __shared__ float part[3][BSZ];
    const int i = blockIdx.x;
    const int j = threadIdx.x & 127;
    const int s = threadIdx.x >> 7;            // 0..3

    float sum = 0.f;
    #pragma unroll 4
    for (int c = s; c < GEMM_GRID; c += 4)
        sum += g_P[c][i * BSZ + j];

    if (s > 0) part[s - 1][j] = sum;
    __syncthreads();
    if (s == 0) {
        sum += part[0][j] + part[1][j] + part[2][j];
        const float sq = g_x2[i] + g_y2[j] - 2.f * sum;
        g_C[i * BSZ + j] = sqrtf(fmaxf(sq, 0.f));
    }
}

// ============================================================
// Kernel 4: Sinkhorn (early exit @2e-6, min 8 iters) — unchanged
// ============================================================
__global__ void __launch_bounds__(512, 1)
sinkhorn_kernel(float* __restrict__ out)
{
    __shared__ __align__(16) float evp[144];   // padded exp(-v)
    __shared__ __align__(16) float eup[144];   // padded exp(-u)
    __shared__ float up[BSZ], vp[BSZ];
    __shared__ float red[16];

    const int t    = threadIdx.x;
    const int lane = t & 31;
    const int q    = lane & 3;
    const int r    = t >> 2;
    const int sidx = r + ((r >> 5) << 2);      // pad-index for publishing

    const float LOGA = -4.852030263919617f;    // log(1/128)
    const float K2   = REGP * 0.6931471805599453f;  // REG * ln2

    float E[32], Et[32];
    float mrow = -1e30f;
    {
        const float4* c4p = reinterpret_cast<const float4*>(g_C + r * BSZ + q * 32);
        #pragma unroll
        for (int k4 = 0; k4 < 8; k4++) {
            float4 c4 = c4p[k4];
            E[k4*4+0]=c4.x; E[k4*4+1]=c4.y; E[k4*4+2]=c4.z; E[k4*4+3]=c4.w;
            mrow = fmaxf(mrow, fmaxf(fmaxf(c4.x, c4.y), fmaxf(c4.z, c4.w)));
        }
    }
    mrow = fmaxf(mrow, __shfl_xor_sync(0xFFFFFFFFu, mrow, 1));
    mrow = fmaxf(mrow, __shfl_xor_sync(0xFFFFFFFFu, mrow, 2));
    #pragma unroll
    for (int k = 0; k < 32; k++) E[k] = __expf(E[k] - mrow);

    float mcol = -1e30f;
    #pragma unroll
    for (int k = 0; k < 32; k++) {
        float cvv = g_C[(q * 32 + k) * BSZ + r];
        Et[k] = cvv;
        mcol = fmaxf(mcol, cvv);
    }
    mcol = fmaxf(mcol, __shfl_xor_sync(0xFFFFFFFFu, mcol, 1));
    mcol = fmaxf(mcol, __shfl_xor_sync(0xFFFFFFFFu, mcol, 2));
    #pragma unroll
    for (int k = 0; k < 32; k++) Et[k] = __expf(Et[k] - mcol);

    const float cu = REGP * (LOGA - mrow);
    const float cv = REGP * (LOGA - mcol);

    float ureg = 0.f, vreg = 0.f;

    if (t < 144) { evp[t] = 1.f; eup[t] = 1.f; }
    __syncthreads();

    const float4* evq = reinterpret_cast<const float4*>(evp + q * 36);
    const float4* euq = reinterpret_cast<const float4*>(eup + q * 36);

    bool done = false;
    for (int it = 0; it < NUM_ITER && !done; ++it) {
        float s0=0.f, s1=0.f, s2=0.f, s3=0.f;
        #pragma unroll
        for (int k4 = 0; k4 < 8; k4++) {
            float4 w = evq[k4];
            s0 = fmaf(E[k4*4+0], w.x, s0);
            s1 = fmaf(E[k4*4+1], w.y, s1);
            s2 = fmaf(E[k4*4+2], w.z, s2);
            s3 = fmaf(E[k4*4+3], w.w, s3);
        }
        float S = (s0 + s1) + (s2 + s3);
        S += __shfl_xor_sync(0xFFFFFFFFu, S, 1);
        S += __shfl_xor_sync(0xFFFFFFFFu, S, 2);
        float un = fmaf(REGP, ureg, cu) - K2 * __log2f(S);
        eup[sidx] = __expf(-un);
        float du = fabsf(un - ureg);
        ureg = un;
        int convu = __syncthreads_and(du < 2e-6f);

        float t0=0.f, t1=0.f, t2=0.f, t3=0.f;
        #pragma unroll
        for (int k4 = 0; k4 < 8; k4++) {
            float4 w = euq[k4];
            t0 = fmaf(Et[k4*4+0], w.x, t0);
            t1 = fmaf(Et[k4*4+1], w.y, t1);
            t2 = fmaf(Et[k4*4+2], w.z, t2);
            t3 = fmaf(Et[k4*4+3], w.w, t3);
        }
        float T = (t0 + t1) + (t2 + t3);
        T += __shfl_xor_sync(0xFFFFFFFFu, T, 1);
        T += __shfl_xor_sync(0xFFFFFFFFu, T, 2);
        float vn = fmaf(REGP, vreg, cv) - K2 * __log2f(T);
        evp[sidx] = __expf(-vn);
        float dv = fabsf(vn - vreg);
        vreg = vn;
        int convv = __syncthreads_and(dv < 2e-6f);

        done = (it >= 8) && (convu != 0) && (convv != 0);
    }

    up[r] = ureg;
    vp[r] = vreg;
    __syncthreads();
    float s = (t < BSZ) ? (up[t] + vp[t]) : 0.f;
    #pragma unroll
    for (int o = 16; o > 0; o >>= 1)
        s += __shfl_xor_sync(0xFFFFFFFFu, s, o);
    if (lane == 0) red[t >> 5] = s;
    __syncthreads();
    if (t == 0)
        out[0] = (red[0] + red[1] + red[2] + red[3]) * (1.0f / BSZ);
}

// ============================================================
extern "C" void kernel_launch(void* const* d_in, const int* in_sizes, int n_in,
                              void* d_out, int out_size)
{
    const float* imgs  = (const float*)d_in[0];
    const float* imgsw = (const float*)d_in[1];
    const float* tgt   = (const float*)d_in[2];
    float* out = (float*)d_out;

    gemm_kernel<<<GEMM_GRID, 512>>>(imgs, imgsw, tgt);
    norm_reduce_kernel<<<1, BSZ>>>();
    cost_kernel<<<BSZ, 512>>>();
    sinkhorn_kernel<<<1, 512>>>(out);
}

// round 13
// speedup vs baseline: 1.1330x; 1.1330x over previous
#include <cuda_runtime.h>
#include <cuda_bf16.h>
#include <cstdint>

#define GEMM_GRID 148
#define BSZ       128
#define DEL       196608          // 3*256*256
#define KC        64              // K elements per chunk (fp8: 64B smem rows)
#define NCHUNK    (DEL / KC)      // 3072
#define REGP      0.01f
#define NUM_ITER  100
#define SW        20              // smem row stride in uint32 words (16 data + 4 pad)

// -------- deterministic global scratch (no allocations allowed) --------
__device__ float g_P [GEMM_GRID][BSZ * BSZ]; // split-K partial dot products
__device__ float g_xp[GEMM_GRID][BSZ];       // partial ||delta||^2
__device__ float g_yp[GEMM_GRID][BSZ];       // partial ||target||^2
__device__ float g_C [BSZ * BSZ];            // cost matrix

// pack 4 fp32 -> 4 e4m3 bytes (byte0 = a .. byte3 = d)
__device__ __forceinline__ uint32_t pack_e4m3x4(float a, float b, float c, float d) {
    uint16_t lo, hi;
    asm("cvt.rn.satfinite.e4m3x2.f32 %0, %1, %2;" : "=h"(lo) : "f"(b), "f"(a));
    asm("cvt.rn.satfinite.e4m3x2.f32 %0, %1, %2;" : "=h"(hi) : "f"(d), "f"(c));
    return (uint32_t)lo | ((uint32_t)hi << 16);
}

// ============================================================
// Kernel 1: split-K GEMM (fp8 e4m3 m16n8k32) + fp32 row norms.
//   512 threads / 16 warps, KC=64 (20.75 chunks/CTA).
//   Iteration for chunk c:
//     1. pack(c+G): raw fp32 regs -> 8 packed fp8 regs (+norms)
//        [loads issued a FULL chunk cycle earlier -> no stall]
//     2. ldg(c+2G) into the freed raw regs
//     3. mma(buf = chunk c)
//     4. sts(c+G) from packed regs  [pure STS, no scoreboard]
//     5. barrier
// ============================================================
__global__ void __launch_bounds__(512, 1)
gemm_kernel(const float* __restrict__ imgs,
            const float* __restrict__ imgsw,
            const float* __restrict__ tgt)
{
    __shared__ uint32_t sA[2][BSZ * SW];
    __shared__ uint32_t sB[2][BSZ * SW];

    const int tid  = threadIdx.x;
    const int lane = tid & 31;
    const int warp = tid >> 5;           // 0..15

    // loader mapping: 8 lanes cover one row's 256B (f and f+8 float4s)
    const int g8 = lane >> 3;            // 0..3
    const int f  = lane & 7;

    // mma mapping: 4x4 warp grid of 32x32 tiles
    const int m0 = (warp & 3) * 32;
    const int n0 = (warp >> 2) * 32;
    const int g  = lane >> 2;
    const int tg = lane & 3;

    float acc[2][4][4];
    #pragma unroll
    for (int a = 0; a < 2; a++)
        #pragma unroll
        for (int b = 0; b < 4; b++)
            #pragma unroll
            for (int cc = 0; cc < 4; cc++) acc[a][b][cc] = 0.f;

    float sx[2] = {0.f, 0.f};
    float sy[2] = {0.f, 0.f};

    float4   ra[4], rw[4], rt[4];        // raw prefetch (48 regs)
    uint32_t pA[4], pB[4];               // packed chunk (8 regs)

    auto ldg_chunk = [&](int c) {
        #pragma unroll
        for (int k = 0; k < 2; k++) {
            const int row = warp * 8 + g8 + 4 * k;        // 0..127
            const size_t base = (size_t)row * (DEL / 4) + (size_t)c * 16 + f;
            ra[2*k  ] = reinterpret_cast<const float4*>(imgs )[base    ];
            ra[2*k+1] = reinterpret_cast<const float4*>(imgs )[base + 8];
            rw[2*k  ] = reinterpret_cast<const float4*>(imgsw)[base    ];
            rw[2*k+1] = reinterpret_cast<const float4*>(imgsw)[base + 8];
            rt[2*k  ] = reinterpret_cast<const float4*>(tgt  )[base    ];
            rt[2*k+1] = reinterpret_cast<const float4*>(tgt  )[base + 8];
        }
    };

    // raw -> packed fp8 regs, accumulate norms (consumes ra/rw/rt)
    auto pack_chunk = [&]() {
        #pragma unroll
        for (int k = 0; k < 2; k++) {
            float4 d0 = make_float4(rw[2*k].x - ra[2*k].x, rw[2*k].y - ra[2*k].y,
                                    rw[2*k].z - ra[2*k].z, rw[2*k].w - ra[2*k].w);
            float4 d1 = make_float4(rw[2*k+1].x - ra[2*k+1].x, rw[2*k+1].y - ra[2*k+1].y,
                                    rw[2*k+1].z - ra[2*k+1].z, rw[2*k+1].w - ra[2*k+1].w);
            sx[k] += d0.x*d0.x + d0.y*d0.y + d0.z*d0.z + d0.w*d0.w
                   + d1.x*d1.x + d1.y*d1.y + d1.z*d1.z + d1.w*d1.w;
            float4 t0 = rt[2*k], t1 = rt[2*k+1];
            sy[k] += t0.x*t0.x + t0.y*t0.y + t0.z*t0.z + t0.w*t0.w
                   + t1.x*t1.x + t1.y*t1.y + t1.z*t1.z + t1.w*t1.w;
            pA[2*k  ] = pack_e4m3x4(d0.x, d0.y, d0.z, d0.w);
            pA[2*k+1] = pack_e4m3x4(d1.x, d1.y, d1.z, d1.w);
            pB[2*k  ] = pack_e4m3x4(t0.x, t0.y, t0.z, t0.w);
            pB[2*k+1] = pack_e4m3x4(t1.x, t1.y, t1.z, t1.w);
        }
    };

    auto sts_packed = [&](int st) {
        #pragma unroll
        for (int k = 0; k < 2; k++) {
            const int row = warp * 8 + g8 + 4 * k;
            sA[st][row * SW + f    ] = pA[2*k  ];
            sA[st][row * SW + 8 + f] = pA[2*k+1];
            sB[st][row * SW + f    ] = pB[2*k  ];
            sB[st][row * SW + 8 + f] = pB[2*k+1];
        }
    };

    auto mma_buf = [&](int st) {
        #pragma unroll
        for (int kk = 0; kk < 2; kk++) {        // two K=32 steps
            uint32_t A0[2], A1[2], A2[2], A3[2];
            #pragma unroll
            for (int mt = 0; mt < 2; mt++) {
                const int row = m0 + mt * 16 + g;
                A0[mt] = sA[st][ row      * SW + kk * 8 + tg    ];
                A1[mt] = sA[st][(row + 8) * SW + kk * 8 + tg    ];
                A2[mt] = sA[st][ row      * SW + kk * 8 + tg + 4];
                A3[mt] = sA[st][(row + 8) * SW + kk * 8 + tg + 4];
            }
            #pragma unroll
            for (int nt = 0; nt < 4; nt++) {
                const int nrow = n0 + nt * 8 + g;
                uint32_t b0 = sB[st][nrow * SW + kk * 8 + tg    ];
                uint32_t b1 = sB[st][nrow * SW + kk * 8 + tg + 4];
                #pragma unroll
                for (int mt = 0; mt < 2; mt++) {
                    asm volatile(
                        "mma.sync.aligned.m16n8k32.row.col.f32.e4m3.e4m3.f32 "
                        "{%0,%1,%2,%3}, {%4,%5,%6,%7}, {%8,%9}, {%0,%1,%2,%3};"
                        : "+f"(acc[mt][nt][0]), "+f"(acc[mt][nt][1]),
                          "+f"(acc[mt][nt][2]), "+f"(acc[mt][nt][3])
                        : "r"(A0[mt]), "r"(A1[mt]), "r"(A2[mt]), "r"(A3[mt]),
                          "r"(b0), "r"(b1));
                }
            }
        }
    };

    const int c0 = blockIdx.x;
    const int G  = GEMM_GRID;

    // prologue: chunk c0 staged into buf0; chunk c0+G loads in flight
    ldg_chunk(c0);
    pack_chunk();
    sts_packed(0);
    if (c0 + G < NCHUNK) ldg_chunk(c0 + G);
    __syncthreads();

    int st = 0;
    for (int c = c0; c < NCHUNK; c += G) {
        const int cn = c + G;
        if (cn < NCHUNK)     pack_chunk();        // loads arrived long ago
        if (cn + G < NCHUNK) ldg_chunk(cn + G);   // into freed raw regs
        mma_buf(st);                              // chunk c
        if (cn < NCHUNK)     sts_packed(st ^ 1);  // pure STS
        __syncthreads();
        st ^= 1;
    }

    // write split-K partials (each warp its 32x32 tile)
    float* P = g_P[blockIdx.x];
    #pragma unroll
    for (int mt = 0; mt < 2; mt++) {
        #pragma unroll
        for (int nt = 0; nt < 4; nt++) {
            const int row = m0 + mt * 16 + g;
            const int col = n0 + nt * 8 + tg * 2;
            float2* p0 = reinterpret_cast<float2*>(&P[ row      * BSZ + col]);
            float2* p1 = reinterpret_cast<float2*>(&P[(row + 8) * BSZ + col]);
            *p0 = make_float2(acc[mt][nt][0], acc[mt][nt][1]);
            *p1 = make_float2(acc[mt][nt][2], acc[mt][nt][3]);
        }
    }

    // norm partials: 8 lanes (f=0..7) share a row
    #pragma unroll
    for (int k = 0; k < 2; k++) {
        float x = sx[k], y = sy[k];
        x += __shfl_xor_sync(0xFFFFFFFFu, x, 1);
        x += __shfl_xor_sync(0xFFFFFFFFu, x, 2);
        x += __shfl_xor_sync(0xFFFFFFFFu, x, 4);
        y += __shfl_xor_sync(0xFFFFFFFFu, y, 1);
        y += __shfl_xor_sync(0xFFFFFFFFu, y, 2);
        y += __shfl_xor_sync(0xFFFFFFFFu, y, 4);
        if (f == 0) {
            const int row = warp * 8 + g8 + 4 * k;
            g_xp[blockIdx.x][row] = x;
            g_yp[blockIdx.x][row] = y;
        }
    }
}

// ============================================================
// Kernel 2: reduce split-K partials + norms, build C (fused).
//   128 blocks x 512 threads; norm reductions done redundantly
//   per block (tiny arrays, L2-resident).
// ============================================================
__global__ void __launch_bounds__(512, 1)
cost_kernel()
{
    __shared__ float part[3][BSZ];
    __shared__ float ny[BSZ];
    __shared__ float pxi[BSZ];
    __shared__ float nx_sh;

    const int i = blockIdx.x;
    const int j = threadIdx.x & 127;
    const int s = threadIdx.x >> 7;            // 0..3

    // main split-K reduction (4 slices)
    float sum = 0.f;
    #pragma unroll 4
    for (int c = s; c < GEMM_GRID; c += 4)
        sum += g_P[c][i * BSZ + j];
    if (s > 0) part[s - 1][j] = sum;

    // s==1 slice also reduces the norm arrays
    if (s == 1) {
        float y = 0.f;
        #pragma unroll 4
        for (int c = 0; c < GEMM_GRID; c++) y += g_yp[c][j];
        ny[j] = y;
        float x = g_xp[j][i];
        if (j + 128 < GEMM_GRID) x += g_xp[j + 128][i];
        pxi[j] = x;
    }
    __syncthreads();

    if (threadIdx.x < 32) {        // reduce pxi[128] -> nx
        float x = pxi[threadIdx.x] + pxi[threadIdx.x + 32]
                + pxi[threadIdx.x + 64] + pxi[threadIdx.x + 96];
        #pragma unroll
        for (int o = 16; o > 0; o >>= 1)
            x += __shfl_xor_sync(0xFFFFFFFFu, x, o);
        if (threadIdx.x == 0) nx_sh = x;
    }
    __syncthreads();

    if (s == 0) {
        sum += part[0][j] + part[1][j] + part[2][j];
        const float sq = nx_sh + ny[j] - 2.f * sum;
        g_C[i * BSZ + j] = sqrtf(fmaxf(sq, 0.f));
    }
}

// ============================================================
// Kernel 3: Sinkhorn (early exit @2e-6, min 8 iters) — unchanged
// ============================================================
__global__ void __launch_bounds__(512, 1)
sinkhorn_kernel(float* __restrict__ out)
{
    __shared__ __align__(16) float evp[144];   // padded exp(-v)
    __shared__ __align__(16) float eup[144];   // padded exp(-u)
    __shared__ float up[BSZ], vp[BSZ];
    __shared__ float red[16];

    const int t    = threadIdx.x;
    const int lane = t & 31;
    const int q    = lane & 3;
    const int r    = t >> 2;
    const int sidx = r + ((r >> 5) << 2);      // pad-index for publishing

    const float LOGA = -4.852030263919617f;    // log(1/128)
    const float K2   = REGP * 0.6931471805599453f;  // REG * ln2

    float E[32], Et[32];
    float mrow = -1e30f;
    {
        const float4* c4p = reinterpret_cast<const float4*>(g_C + r * BSZ + q * 32);
        #pragma unroll
        for (int k4 = 0; k4 < 8; k4++) {
            float4 c4 = c4p[k4];
            E[k4*4+0]=c4.x; E[k4*4+1]=c4.y; E[k4*4+2]=c4.z; E[k4*4+3]=c4.w;
            mrow = fmaxf(mrow, fmaxf(fmaxf(c4.x, c4.y), fmaxf(c4.z, c4.w)));
        }
    }
    mrow = fmaxf(mrow, __shfl_xor_sync(0xFFFFFFFFu, mrow, 1));
    mrow = fmaxf(mrow, __shfl_xor_sync(0xFFFFFFFFu, mrow, 2));
    #pragma unroll
    for (int k = 0; k < 32; k++) E[k] = __expf(E[k] - mrow);

    float mcol = -1e30f;
    #pragma unroll
    for (int k = 0; k < 32; k++) {
        float cvv = g_C[(q * 32 + k) * BSZ + r];
        Et[k] = cvv;
        mcol = fmaxf(mcol, cvv);
    }
    mcol = fmaxf(mcol, __shfl_xor_sync(0xFFFFFFFFu, mcol, 1));
    mcol = fmaxf(mcol, __shfl_xor_sync(0xFFFFFFFFu, mcol, 2));
    #pragma unroll
    for (int k = 0; k < 32; k++) Et[k] = __expf(Et[k] - mcol);

    const float cu = REGP * (LOGA - mrow);
    const float cv = REGP * (LOGA - mcol);

    float ureg = 0.f, vreg = 0.f;

    if (t < 144) { evp[t] = 1.f; eup[t] = 1.f; }
    __syncthreads();

    const float4* evq = reinterpret_cast<const float4*>(evp + q * 36);
    const float4* euq = reinterpret_cast<const float4*>(eup + q * 36);

    bool done = false;
    for (int it = 0; it < NUM_ITER && !done; ++it) {
        float s0=0.f, s1=0.f, s2=0.f, s3=0.f;
        #pragma unroll
        for (int k4 = 0; k4 < 8; k4++) {
            float4 w = evq[k4];
            s0 = fmaf(E[k4*4+0], w.x, s0);
            s1 = fmaf(E[k4*4+1], w.y, s1);
            s2 = fmaf(E[k4*4+2], w.z, s2);
            s3 = fmaf(E[k4*4+3], w.w, s3);
        }
        float S = (s0 + s1) + (s2 + s3);
        S += __shfl_xor_sync(0xFFFFFFFFu, S, 1);
        S += __shfl_xor_sync(0xFFFFFFFFu, S, 2);
        float un = fmaf(REGP, ureg, cu) - K2 * __log2f(S);
        eup[sidx] = __expf(-un);
        float du = fabsf(un - ureg);
        ureg = un;
        int convu = __syncthreads_and(du < 2e-6f);

        float t0=0.f, t1=0.f, t2=0.f, t3=0.f;
        #pragma unroll
        for (int k4 = 0; k4 < 8; k4++) {
            float4 w = euq[k4];
            t0 = fmaf(Et[k4*4+0], w.x, t0);
            t1 = fmaf(Et[k4*4+1], w.y, t1);
            t2 = fmaf(Et[k4*4+2], w.z, t2);
            t3 = fmaf(Et[k4*4+3], w.w, t3);
        }
        float T = (t0 + t1) + (t2 + t3);
        T += __shfl_xor_sync(0xFFFFFFFFu, T, 1);
        T += __shfl_xor_sync(0xFFFFFFFFu, T, 2);
        float vn = fmaf(REGP, vreg, cv) - K2 * __log2f(T);
        evp[sidx] = __expf(-vn);
        float dv = fabsf(vn - vreg);
        vreg = vn;
        int convv = __syncthreads_and(dv < 2e-6f);

        done = (it >= 8) && (convu != 0) && (convv != 0);
    }

    up[r] = ureg;
    vp[r] = vreg;
    __syncthreads();
    float s = (t < BSZ) ? (up[t] + vp[t]) : 0.f;
    #pragma unroll
    for (int o = 16; o > 0; o >>= 1)
        s += __shfl_xor_sync(0xFFFFFFFFu, s, o);
    if (lane == 0) red[t >> 5] = s;
    __syncthreads();
    if (t == 0)
        out[0] = (red[0] + red[1] + red[2] + red[3]) * (1.0f / BSZ);
}

// ============================================================
extern "C" void kernel_launch(void* const* d_in, const int* in_sizes, int n_in,
                              void* d_out, int out_size)
{
    const float* imgs  = (const float*)d_in[0];
    const float* imgsw = (const float*)d_in[1];
    const float* tgt   = (const float*)d_in[2];
    float* out = (float*)d_out;

    gemm_kernel<<<GEMM_GRID, 512>>>(imgs, imgsw, tgt);
    cost_kernel<<<BSZ, 512>>>();
    sinkhorn_kernel<<<1, 512>>>(out);
}

// round 15
// speedup vs baseline: 1.1364x; 1.0030x over previous
#include <cuda_runtime.h>
#include <cuda_bf16.h>
#include <cstdint>

#define GEMM_GRID 296            // 148 K-slices x 2 C-halves
#define KSLICES   148
#define BSZ       128
#define DEL       196608         // 3*256*256
#define KC        32             // K elements per chunk (fp8: 32B smem rows)
#define NCHUNK    (DEL / KC)     // 6144
#define REGP      0.01f
#define NUM_ITER  100
#define SW        12             // smem row stride in words (8 data + 4 pad)

// -------- deterministic global scratch (no allocations allowed) --------
__device__ float g_P  [GEMM_GRID][64 * BSZ]; // [b][localrow*128+col], 9.7MB
__device__ float g_xp2[GEMM_GRID][64];       // ||delta||^2 partials (local rows)
__device__ float g_yp [KSLICES][BSZ];        // ||target||^2 partials (half 0 only)
__device__ float g_C  [BSZ * BSZ];           // cost matrix

// pack 4 fp32 -> 4 e4m3 bytes (byte0 = a .. byte3 = d)
__device__ __forceinline__ uint32_t pack_e4m3x4(float a, float b, float c, float d) {
    uint16_t lo, hi;
    asm("cvt.rn.satfinite.e4m3x2.f32 %0, %1, %2;" : "=h"(lo) : "f"(b), "f"(a));
    asm("cvt.rn.satfinite.e4m3x2.f32 %0, %1, %2;" : "=h"(hi) : "f"(d), "f"(c));
    return (uint32_t)lo | ((uint32_t)hi << 16);
}

// ============================================================
// Kernel 1: split-K GEMM (fp8 e4m3 m16n8k32) + fp32 row norms.
//   296 CTAs x 256 threads, 2 CTAs/SM (one CTA's loads cover the
//   other's barrier/mma phase). CTA b: kslice=b>>1, half=b&1 owns
//   C rows [64*half, 64*half+64) for K chunks kslice+148n.
//   R13 pipeline: pack(c+G) ; ldg(c+2G) ; mma(c) ; sts(c+G) ; BAR.
// ============================================================
__global__ void __launch_bounds__(256, 2)
gemm_kernel(const float* __restrict__ imgs,
            const float* __restrict__ imgsw,
            const float* __restrict__ tgt)
{
    __shared__ uint32_t sA[2][64 * SW];      // delta half-tile (fp8)
    __shared__ uint32_t sB[2][BSZ * SW];     // target tile (fp8)

    const int tid  = threadIdx.x;
    const int lane = tid & 31;
    const int warp = tid >> 5;               // 0..7
    const int b      = blockIdx.x;
    const int kslice = b >> 1;
    const int half   = b & 1;

    // loader mapping: 8 lanes (f) cover one row's 128B; rB = base row
    const int f  = tid & 7;
    const int rB = tid >> 3;                 // 0..31

    // mma mapping: 4x2 warp grid of 16x64 tiles over the 64x128 C half
    const int m0 = (warp & 3) * 16;
    const int n0 = (warp >> 2) * 64;
    const int g  = lane >> 2;
    const int tg = lane & 3;

    float acc[8][4];
    #pragma unroll
    for (int nt = 0; nt < 8; nt++)
        #pragma unroll
        for (int cc = 0; cc < 4; cc++) acc[nt][cc] = 0.f;

    float sx[2] = {0.f, 0.f};
    float sy[4] = {0.f, 0.f, 0.f, 0.f};

    float4   rb4[4];                         // target raw (16 floats)
    float4   ia4[2], iw4[2];                 // imgs/imgsw raw (16 floats)
    uint32_t pB[4], pA[2];                   // packed fp8

    auto ldg_chunk = [&](int c) {
        #pragma unroll
        for (int k = 0; k < 4; k++) {
            const int row = rB + 32 * k;     // 0..127
            rb4[k] = reinterpret_cast<const float4*>(tgt)
                        [(size_t)row * (DEL / 4) + (size_t)c * 8 + f];
        }
        #pragma unroll
        for (int k = 0; k < 2; k++) {
            const int row = half * 64 + rB + 32 * k;   // global A row
            const size_t idx = (size_t)row * (DEL / 4) + (size_t)c * 8 + f;
            ia4[k] = reinterpret_cast<const float4*>(imgs )[idx];
            iw4[k] = reinterpret_cast<const float4*>(imgsw)[idx];
        }
    };

    auto pack_chunk = [&]() {
        #pragma unroll
        for (int k = 0; k < 4; k++) {
            float4 t = rb4[k];
            sy[k] += t.x*t.x + t.y*t.y + t.z*t.z + t.w*t.w;
            pB[k] = pack_e4m3x4(t.x, t.y, t.z, t.w);
        }
        #pragma unroll
        for (int k = 0; k < 2; k++) {
            float4 d = make_float4(iw4[k].x - ia4[k].x, iw4[k].y - ia4[k].y,
                                   iw4[k].z - ia4[k].z, iw4[k].w - ia4[k].w);
            sx[k] += d.x*d.x + d.y*d.y + d.z*d.z + d.w*d.w;
            pA[k] = pack_e4m3x4(d.x, d.y, d.z, d.w);
        }
    };

    auto sts_packed = [&](int st) {
        #pragma unroll
        for (int k = 0; k < 4; k++)
            sB[st][(rB + 32 * k) * SW + f] = pB[k];
        #pragma unroll
        for (int k = 0; k < 2; k++)
            sA[st][(rB + 32 * k) * SW + f] = pA[k];
    };

    auto mma_buf = [&](int st) {
        const uint32_t A0 = sA[st][(m0 + g    ) * SW + tg    ];
        const uint32_t A1 = sA[st][(m0 + 8 + g) * SW + tg    ];
        const uint32_t A2 = sA[st][(m0 + g    ) * SW + tg + 4];
        const uint32_t A3 = sA[st][(m0 + 8 + g) * SW + tg + 4];
        #pragma unroll
        for (int nt = 0; nt < 8; nt++) {
            const int nrow = n0 + nt * 8 + g;
            const uint32_t b0 = sB[st][nrow * SW + tg    ];
            const uint32_t b1 = sB[st][nrow * SW + tg + 4];
            asm volatile(
                "mma.sync.aligned.m16n8k32.row.col.f32.e4m3.e4m3.f32 "
                "{%0,%1,%2,%3}, {%4,%5,%6,%7}, {%8,%9}, {%0,%1,%2,%3};"
                : "+f"(acc[nt][0]), "+f"(acc[nt][1]),
                  "+f"(acc[nt][2]), "+f"(acc[nt][3])
                : "r"(A0), "r"(A1), "r"(A2), "r"(A3), "r"(b0), "r"(b1));
        }
    };

    const int c0 = kslice;
    const int G  = KSLICES;

    // prologue
    ldg_chunk(c0);
    pack_chunk();
    sts_packed(0);
    if (c0 + G < NCHUNK) ldg_chunk(c0 + G);
    __syncthreads();

    int st = 0;
    for (int c = c0; c < NCHUNK; c += G) {
        const int cn = c + G;
        if (cn < NCHUNK)     pack_chunk();        // loads arrived a chunk ago
        if (cn + G < NCHUNK) ldg_chunk(cn + G);   // into freed raw regs
        mma_buf(st);                              // chunk c
        if (cn < NCHUNK)     sts_packed(st ^ 1);  // pure STS
        __syncthreads();
        st ^= 1;
    }

    // write split-K partials: rows m0+g and m0+8+g of the 64x128 half-tile
    float* P = g_P[b];
    #pragma unroll
    for (int nt = 0; nt < 8; nt++) {
        const int col = n0 + nt * 8 + tg * 2;
        float2* p0 = reinterpret_cast<float2*>(&P[(m0 + g    ) * BSZ + col]);
        float2* p1 = reinterpret_cast<float2*>(&P[(m0 + 8 + g) * BSZ + col]);
        *p0 = make_float2(acc[nt][0], acc[nt][1]);
        *p1 = make_float2(acc[nt][2], acc[nt][3]);
    }

    // norms: 8 lanes (f) share a row
    #pragma unroll
    for (int k = 0; k < 2; k++) {
        float x = sx[k];
        x += __shfl_xor_sync(0xFFFFFFFFu, x, 1);
        x += __shfl_xor_sync(0xFFFFFFFFu, x, 2);
        x += __shfl_xor_sync(0xFFFFFFFFu, x, 4);
        if (f == 0) g_xp2[b][rB + 32 * k] = x;
    }
    if (half == 0) {
        #pragma unroll
        for (int k = 0; k < 4; k++) {
            float y = sy[k];
            y += __shfl_xor_sync(0xFFFFFFFFu, y, 1);
            y += __shfl_xor_sync(0xFFFFFFFFu, y, 2);
            y += __shfl_xor_sync(0xFFFFFFFFu, y, 4);
            if (f == 0) g_yp[kslice][rB + 32 * k] = y;
        }
    }
}

// ============================================================
// Kernel 2: reduce split-K partials + norms, build C (fused).
// ============================================================
__global__ void __launch_bounds__(512, 1)
cost_kernel()
{
    __shared__ float part[3][BSZ];
    __shared__ float ny[BSZ];
    __shared__ float pxi[BSZ];
    __shared__ float nx_sh;

    const int i  = blockIdx.x;
    const int j  = threadIdx.x & 127;
    const int s  = threadIdx.x >> 7;           // 0..3
    const int hi = i >> 6;                     // which C half
    const int il = i & 63;                     // local row

    float sum = 0.f;
    #pragma unroll 4
    for (int c = s; c < KSLICES; c += 4)
        sum += g_P[2 * c + hi][il * BSZ + j];
    if (s > 0) part[s - 1][j] = sum;

    if (s == 1) {
        float y = 0.f;
        #pragma unroll 4
        for (int c = 0; c < KSLICES; c++) y += g_yp[c][j];
        ny[j] = y;
        float x = g_xp2[2 * j + hi][il];
        if (j + 128 < KSLICES) x += g_xp2[2 * (j + 128) + hi][il];
        pxi[j] = x;
    }
    __syncthreads();

    if (threadIdx.x < 32) {
        float x = pxi[threadIdx.x] + pxi[threadIdx.x + 32]
                + pxi[threadIdx.x + 64] + pxi[threadIdx.x + 96];
        #pragma unroll
        for (int o = 16; o > 0; o >>= 1)
            x += __shfl_xor_sync(0xFFFFFFFFu, x, o);
        if (threadIdx.x == 0) nx_sh = x;
    }
    __syncthreads();

    if (s == 0) {
        sum += part[0][j] + part[1][j] + part[2][j];
        const float sq = nx_sh + ny[j] - 2.f * sum;
        g_C[i * BSZ + j] = sqrtf(fmaxf(sq, 0.f));
    }
}

// ============================================================
// Kernel 3: Sinkhorn (early exit @2e-6, min 8 iters) — unchanged
// ============================================================
__global__ void __launch_bounds__(512, 1)
sinkhorn_kernel(float* __restrict__ out)
{
    __shared__ __align__(16) float evp[144];
    __shared__ __align__(16) float eup[144];
    __shared__ float up[BSZ], vp[BSZ];
    __shared__ float red[16];

    const int t    = threadIdx.x;
    const int lane = t & 31;
    const int q    = lane & 3;
    const int r    = t >> 2;
    const int sidx = r + ((r >> 5) << 2);

    const float LOGA = -4.852030263919617f;
    const float K2   = REGP * 0.6931471805599453f;

    float E[32], Et[32];
    float mrow = -1e30f;
    {
        const float4* c4p = reinterpret_cast<const float4*>(g_C + r * BSZ + q * 32);
        #pragma unroll
        for (int k4 = 0; k4 < 8; k4++) {
            float4 c4 = c4p[k4];
            E[k4*4+0]=c4.x; E[k4*4+1]=c4.y; E[k4*4+2]=c4.z; E[k4*4+3]=c4.w;
            mrow = fmaxf(mrow, fmaxf(fmaxf(c4.x, c4.y), fmaxf(c4.z, c4.w)));
        }
    }
    mrow = fmaxf(mrow, __shfl_xor_sync(0xFFFFFFFFu, mrow, 1));
    mrow = fmaxf(mrow, __shfl_xor_sync(0xFFFFFFFFu, mrow, 2));
    #pragma unroll
    for (int k = 0; k < 32; k++) E[k] = __expf(E[k] - mrow);

    float mcol = -1e30f;
    #pragma unroll
    for (int k = 0; k < 32; k++) {
        float cvv = g_C[(q * 32 + k) * BSZ + r];
        Et[k] = cvv;
        mcol = fmaxf(mcol, cvv);
    }
    mcol = fmaxf(mcol, __shfl_xor_sync(0xFFFFFFFFu, mcol, 1));
    mcol = fmaxf(mcol, __shfl_xor_sync(0xFFFFFFFFu, mcol, 2));
    #pragma unroll
    for (int k = 0; k < 32; k++) Et[k] = __expf(Et[k] - mcol);

    const float cu = REGP * (LOGA - mrow);
    const float cv = REGP * (LOGA - mcol);

    float ureg = 0.f, vreg = 0.f;

    if (t < 144) { evp[t] = 1.f; eup[t] = 1.f; }
    __syncthreads();

    const float4* evq = reinterpret_cast<const float4*>(evp + q * 36);
    const float4* euq = reinterpret_cast<const float4*>(eup + q * 36);

    bool done = false;
    for (int it = 0; it < NUM_ITER && !done; ++it) {
        float s0=0.f, s1=0.f, s2=0.f, s3=0.f;
        #pragma unroll
        for (int k4 = 0; k4 < 8; k4++) {
            float4 w = evq[k4];
            s0 = fmaf(E[k4*4+0], w.x, s0);
            s1 = fmaf(E[k4*4+1], w.y, s1);
            s2 = fmaf(E[k4*4+2], w.z, s2);
            s3 = fmaf(E[k4*4+3], w.w, s3);
        }
        float S = (s0 + s1) + (s2 + s3);
        S += __shfl_xor_sync(0xFFFFFFFFu, S, 1);
        S += __shfl_xor_sync(0xFFFFFFFFu, S, 2);
        float un = fmaf(REGP, ureg, cu) - K2 * __log2f(S);
        eup[sidx] = __expf(-un);
        float du = fabsf(un - ureg);
        ureg = un;
        int convu = __syncthreads_and(du < 2e-6f);

        float t0=0.f, t1=0.f, t2=0.f, t3=0.f;
        #pragma unroll
        for (int k4 = 0; k4 < 8; k4++) {
            float4 w = euq[k4];
            t0 = fmaf(Et[k4*4+0], w.x, t0);
            t1 = fmaf(Et[k4*4+1], w.y, t1);
            t2 = fmaf(Et[k4*4+2], w.z, t2);
            t3 = fmaf(Et[k4*4+3], w.w, t3);
        }
        float T = (t0 + t1) + (t2 + t3);
        T += __shfl_xor_sync(0xFFFFFFFFu, T, 1);
        T += __shfl_xor_sync(0xFFFFFFFFu, T, 2);
        float vn = fmaf(REGP, vreg, cv) - K2 * __log2f(T);
        evp[sidx] = __expf(-vn);
        float dv = fabsf(vn - vreg);
        vreg = vn;
        int convv = __syncthreads_and(dv < 2e-6f);

        done = (it >= 8) && (convu != 0) && (convv != 0);
    }

    up[r] = ureg;
    vp[r] = vreg;
    __syncthreads();
    float s = (t < BSZ) ? (up[t] + vp[t]) : 0.f;
    #pragma unroll
    for (int o = 16; o > 0; o >>= 1)
        s += __shfl_xor_sync(0xFFFFFFFFu, s, o);
    if (lane == 0) red[t >> 5] = s;
    __syncthreads();
    if (t == 0)
        out[0] = (red[0] + red[1] + red[2] + red[3]) * (1.0f / BSZ);
}

// ============================================================
extern "C" void kernel_launch(void* const* d_in, const int* in_sizes, int n_in,
                              void* d_out, int out_size)
{
    const float* imgs  = (const float*)d_in[0];
    const float* imgsw = (const float*)d_in[1];
    const float* tgt   = (const float*)d_in[2];
    float* out = (float*)d_out;

    gemm_kernel<<<GEMM_GRID, 256>>>(imgs, imgsw, tgt);
    cost_kernel<<<BSZ, 512>>>();
    sinkhorn_kernel<<<1, 512>>>(out);
}